// round 5
// baseline (speedup 1.0000x reference)
#include <cuda_runtime.h>
#include <cub/cub.cuh>
#include <cstdint>

static constexpr int MAX_E = 1600000;             // < 2^21 (orig id fits 21 bits)
static constexpr int CHUNK = 256;                 // arrwp rows per pipeline stage
static constexpr int SCAN_TILE = 2048;            // 256 thr x 8 items
static constexpr int MAX_BLK = (MAX_E + SCAN_TILE - 1) / SCAN_TILE;

// Scratch (allocation-free: __device__ globals)
__device__ unsigned long long g_k64_a[MAX_E];     // (key<<21)|orig
__device__ unsigned long long g_k64_b[MAX_E];
__device__ uint32_t g_segflag[MAX_E];             // per ORIGINAL edge: (seg<<1)|leader
__device__ unsigned long long g_desc[MAX_BLK];    // lookback: (value<<2)|state
__device__ int g_blkctr;
__device__ int g_nu;
__device__ unsigned char g_cub_temp[64 * 1024 * 1024];

// ---------------------------------------------------------------------------
__device__ __forceinline__ uint32_t smem_u32(const void* p) {
    uint32_t a;
    asm("{ .reg .u64 t; cvta.to.shared.u64 t, %1; cvt.u32.u64 %0, t; }"
        : "=r"(a) : "l"(p));
    return a;
}
__device__ __forceinline__ void fma2(unsigned long long& acc,
                                     unsigned long long a, unsigned long long b) {
    asm("fma.rn.f32x2 %0, %1, %2, %0;" : "+l"(acc) : "l"(a), "l"(b));
}
__device__ __forceinline__ void mbar_init(uint32_t mbar, uint32_t cnt) {
    asm volatile("mbarrier.init.shared.b64 [%0], %1;" :: "r"(mbar), "r"(cnt) : "memory");
}
__device__ __forceinline__ void mbar_expect_tx(uint32_t mbar, uint32_t bytes) {
    asm volatile("mbarrier.arrive.expect_tx.shared.b64 _, [%0], %1;"
                 :: "r"(mbar), "r"(bytes) : "memory");
}
__device__ __forceinline__ void mbar_wait(uint32_t mbar, uint32_t parity) {
    uint32_t done;
    asm volatile(
        "{ .reg .pred p; mbarrier.try_wait.parity.acquire.cta.shared::cta.b64 p, [%1], %2;"
        " selp.b32 %0, 1, 0, p; }"
        : "=r"(done) : "r"(mbar), "r"(parity) : "memory");
    if (!done) {
        asm volatile(
            "{ .reg .pred P1; WL%=:"
            " mbarrier.try_wait.parity.acquire.cta.shared::cta.b64 P1, [%0], %1, 0x989680;"
            " @P1 bra.uni WD%=; bra.uni WL%=; WD%=: }"
            :: "r"(mbar), "r"(parity) : "memory");
    }
}
__device__ __forceinline__ void bulk_copy(uint32_t dst, const void* src,
                                          uint32_t bytes, uint32_t mbar) {
    asm volatile(
        "cp.async.bulk.shared::cta.global.mbarrier::complete_tx::bytes [%0], [%1], %2, [%3];"
        :: "r"(dst), "l"(src), "r"(bytes), "r"(mbar) : "memory");
}

// ---------------------------------------------------------------------------
// 1. build packed words: ((row<<16|col) << 21) | orig_id. Also resets the
//    lookback descriptors for this launch (sort runs between -> visible).
__global__ void k_build_keys(const int* __restrict__ ei, const int* __restrict__ ai,
                             int Ee, int Ea, int nblk) {
    int E = Ee + Ea;
    int i = blockIdx.x * blockDim.x + threadIdx.x;
    if (i < nblk) g_desc[i] = 0ull;
    if (i == 0) g_blkctr = 0;
    if (i >= E) return;
    int r, c;
    if (i < Ee) { r = ei[i];          c = ei[Ee + i]; }
    else        { int j = i - Ee; r = ai[j]; c = ai[Ea + j]; }
    uint32_t key = ((uint32_t)r << 16) | (uint32_t)c;
    g_k64_a[i] = ((unsigned long long)key << 21) | (unsigned long long)i;
}

// 2. fused flags + decoupled-lookback scan + inverse map.
//    sums[i] = inclusive scan of boundary flags; segflag[orig] = (seg<<1)|flag.
__global__ void __launch_bounds__(256)
k_seg_scan(int E) {
    const int tid = threadIdx.x;
    __shared__ int s_bid;
    __shared__ int s_wsum[8];
    __shared__ int s_excl;
    if (tid == 0) s_bid = atomicAdd(&g_blkctr, 1);
    __syncthreads();
    const int bid  = s_bid;
    const int base = bid * SCAN_TILE + tid * 8;

    unsigned long long w[8];
    int f[8], ps[8];
    if (base + 8 <= E) {
        const ulonglong2* p = reinterpret_cast<const ulonglong2*>(g_k64_b + base);
        ulonglong2 v0 = p[0], v1 = p[1], v2 = p[2], v3 = p[3];
        w[0]=v0.x; w[1]=v0.y; w[2]=v1.x; w[3]=v1.y;
        w[4]=v2.x; w[5]=v2.y; w[6]=v3.x; w[7]=v3.y;
    } else {
        #pragma unroll
        for (int j = 0; j < 8; j++)
            w[j] = (base + j < E) ? g_k64_b[base + j] : 0ull;
    }
    unsigned long long wp = (base > 0 && base < E) ? g_k64_b[base - 1] : 0ull;
    #pragma unroll
    for (int j = 0; j < 8; j++) {
        int idx = base + j;
        unsigned long long prev = j ? w[j - 1] : wp;
        f[j] = (idx < E) ? ((idx == 0) || ((w[j] >> 21) != (prev >> 21))) : 0;
    }
    int t = 0;
    #pragma unroll
    for (int j = 0; j < 8; j++) { t += f[j]; ps[j] = t; }

    // warp inclusive scan of thread totals
    int lane = tid & 31, wid = tid >> 5;
    int incl = t;
    #pragma unroll
    for (int d = 1; d < 32; d <<= 1) {
        int n = __shfl_up_sync(0xFFFFFFFFu, incl, d);
        if (lane >= d) incl += n;
    }
    if (lane == 31) s_wsum[wid] = incl;
    __syncthreads();
    if (wid == 0) {
        int v = (lane < 8) ? s_wsum[lane] : 0;
        #pragma unroll
        for (int d = 1; d < 8; d <<= 1) {
            int n = __shfl_up_sync(0xFFu, v, d);
            if (lane >= d && lane < 8) v += n;
        }
        if (lane < 8) s_wsum[lane] = v;
    }
    __syncthreads();
    int blockAgg = s_wsum[7];
    int thrExcl  = (wid ? s_wsum[wid - 1] : 0) + (incl - t);

    if (tid == 0) {
        if (bid == 0) {
            atomicExch(&g_desc[0], (((unsigned long long)blockAgg) << 2) | 2ull);
            s_excl = 0;
        } else {
            atomicExch(&g_desc[bid], (((unsigned long long)blockAgg) << 2) | 1ull);
            int excl = 0;
            int j = bid - 1;
            while (true) {
                unsigned long long d = atomicAdd(&g_desc[j], 0ull);
                unsigned st = (unsigned)(d & 3ull);
                if (st == 0) continue;
                excl += (int)(d >> 2);
                if (st == 2) break;
                j--;
            }
            atomicExch(&g_desc[bid],
                       (((unsigned long long)(excl + blockAgg)) << 2) | 2ull);
            s_excl = excl;
        }
    }
    __syncthreads();
    int prefix = s_excl + thrExcl;

    #pragma unroll
    for (int j = 0; j < 8; j++) {
        int idx = base + j;
        if (idx < E) {
            int sums = prefix + ps[j];
            uint32_t orig = (uint32_t)(w[j] & 0x1FFFFFull);
            g_segflag[orig] = ((uint32_t)(sums - 1) << 1) | (uint32_t)f[j];
            if (idx == E - 1) g_nu = sums;
        }
    }
}

// 3. raw-edge copy: one thread per float4 -> maximal MLP, pure bandwidth.
__global__ void k_copy_edges(const int* __restrict__ ei,
                             const float* __restrict__ eattr,
                             float* __restrict__ out, int Ee, int E) {
    int i = blockIdx.x * blockDim.x + threadIdx.x;
    if (i >= Ee * 16) return;
    int e = i >> 4, f4 = i & 15;
    uint32_t sf = g_segflag[e];
    if (!(sf & 1u)) return;
    int seg = (int)(sf >> 1);
    float4 v = reinterpret_cast<const float4*>(eattr)[i];
    float4* out_attr4 = reinterpret_cast<float4*>(out + 2 * (size_t)E);
    out_attr4[(size_t)seg * 16 + f4] = v;
    if (f4 == 0) {
        out[seg]     = (float)ei[e];
        out[E + seg] = (float)ei[Ee + e];
    }
}

// 4. arrwp projection+scatter (unchanged from R4 passing kernel).
static constexpr int SM_FLAG = 16;
static constexpr int SM_ROW  = SM_FLAG + 2 * CHUNK * 4;
static constexpr int SM_COL  = SM_ROW  + 2 * CHUNK * 4;
static constexpr int SM_ATTR = 8192;
static constexpr int SM_TOTAL = SM_ATTR + 2 * CHUNK * 128;

__global__ void __launch_bounds__(256, 2)
k_proj_arrwp(const int* __restrict__ ai, const float* __restrict__ aattr,
             const float* __restrict__ W, float* __restrict__ out,
             int Ee, int Ea) {
    extern __shared__ unsigned char sm[];
    const uint32_t sbase = smem_u32(sm);
    const int E = Ee + Ea;
    float* out_attr = out + 2 * (size_t)E;

    const int tid  = threadIdx.x;
    const int lane = tid & 31;
    const int wrp  = tid >> 5;

    unsigned long long wa[16], wb[16];
    {
        const unsigned long long* Wa =
            reinterpret_cast<const unsigned long long*>(W + lane * 32);
        const unsigned long long* Wb =
            reinterpret_cast<const unsigned long long*>(W + (lane + 32) * 32);
        #pragma unroll
        for (int kk = 0; kk < 16; kk++) { wa[kk] = __ldg(Wa + kk); wb[kk] = __ldg(Wb + kk); }
    }

    const int nChunks = (Ea + CHUNK - 1) / CHUNK;
    if (tid == 0) { mbar_init(sbase + 0, 1); mbar_init(sbase + 8, 1); }
    __syncthreads();

    int c0 = blockIdx.x;
    if (c0 >= nChunks) return;

    auto issue = [&](int c, int s) {
        int base = c * CHUNK;
        int rem  = min(CHUNK, Ea - base);
        bool full = (rem == CHUNK);
        uint32_t attrB = (uint32_t)rem * 128u;
        uint32_t flagB = ((uint32_t)rem * 4u + 15u) & ~15u;
        uint32_t tx = attrB + flagB + (full ? 2048u : 0u);
        uint32_t mb = sbase + s * 8;
        mbar_expect_tx(mb, tx);
        bulk_copy(sbase + SM_ATTR + s * (CHUNK * 128), aattr + (size_t)base * 32, attrB, mb);
        bulk_copy(sbase + SM_FLAG + s * (CHUNK * 4), &g_segflag[Ee + base], flagB, mb);
        if (full) {
            bulk_copy(sbase + SM_ROW + s * (CHUNK * 4), ai + base,      CHUNK * 4, mb);
            bulk_copy(sbase + SM_COL + s * (CHUNK * 4), ai + Ea + base, CHUNK * 4, mb);
        }
    };

    if (tid == 0) issue(c0, 0);
    int phase0 = 0, phase1 = 0;

    int li = 0;
    for (int c = c0; c < nChunks; c += gridDim.x, li++) {
        int s = li & 1;
        int cn = c + gridDim.x;
        if (tid == 0 && cn < nChunks) issue(cn, s ^ 1);

        mbar_wait(sbase + s * 8, s ? phase1 : phase0);
        if (s) phase1 ^= 1; else phase0 ^= 1;

        int base = c * CHUNK;
        int rem  = min(CHUNK, Ea - base);
        bool full = (rem == CHUNK);
        int lbase = wrp * 32;
        if (lbase < rem) {
            int cnt = min(32, rem - lbase);
            const uint32_t* flag_s = (const uint32_t*)(sm + SM_FLAG + s * (CHUNK * 4));
            const int* row_s = (const int*)(sm + SM_ROW + s * (CHUNK * 4));
            const int* col_s = (const int*)(sm + SM_COL + s * (CHUNK * 4));
            const float* attr_s = (const float*)(sm + SM_ATTR + s * (CHUNK * 128));

            uint32_t sfv = (lane < cnt) ? flag_s[lbase + lane] : 0u;
            int rv = 0, cv = 0;
            if (full) { rv = row_s[lbase + lane]; cv = col_s[lbase + lane]; }

            for (int t = 0; t < cnt; t++) {
                uint32_t sfe = __shfl_sync(0xFFFFFFFFu, sfv, t);
                int rr = full ? __shfl_sync(0xFFFFFFFFu, rv, t) : 0;
                int cc = full ? __shfl_sync(0xFFFFFFFFu, cv, t) : 0;
                if (!(sfe & 1u)) continue;
                int seg = (int)(sfe >> 1);
                const unsigned long long* a2 =
                    (const unsigned long long*)(attr_s + (lbase + t) * 32);
                unsigned long long accA = 0ull, accB = 0ull;
                #pragma unroll
                for (int kk = 0; kk < 16; kk++) {
                    unsigned long long av = a2[kk];
                    fma2(accA, av, wa[kk]);
                    fma2(accB, av, wb[kk]);
                }
                float ax, ay, bx, by;
                asm("mov.b64 {%0, %1}, %2;" : "=f"(ax), "=f"(ay) : "l"(accA));
                asm("mov.b64 {%0, %1}, %2;" : "=f"(bx), "=f"(by) : "l"(accB));
                float* orow = out_attr + (size_t)seg * 64;
                orow[lane]      = ax + ay;
                orow[32 + lane] = bx + by;
                if (!full && lane == 0) {
                    int j = base + lbase + t;
                    rr = ai[j]; cc = ai[Ea + j];
                }
                if (lane == 0) {
                    out[seg]     = (float)rr;
                    out[E + seg] = (float)cc;
                }
            }
        }
        __syncthreads();
    }
}

// 5. duplicate scatter: rare; runs AFTER leader kernels (stream order).
__global__ void k_scatter_dups(const float* __restrict__ eattr,
                               const float* __restrict__ aattr,
                               const float* __restrict__ W,
                               float* __restrict__ out, int Ee, int Ea) {
    int E = Ee + Ea;
    int e = blockIdx.x * blockDim.x + threadIdx.x;
    if (e >= E) return;
    uint32_t sf = g_segflag[e];
    if (sf & 1u) return;
    int seg = (int)(sf >> 1);
    float* orow = out + 2 * (size_t)E + (size_t)seg * 64;
    if (e < Ee) {
        const float* a = eattr + (size_t)e * 64;
        for (int j = 0; j < 64; j++) atomicAdd(orow + j, a[j]);
    } else {
        const float* a = aattr + (size_t)(e - Ee) * 32;
        float av[32];
        #pragma unroll
        for (int k = 0; k < 32; k++) av[k] = a[k];
        for (int j = 0; j < 64; j++) {
            float s = 0.f;
            #pragma unroll
            for (int k = 0; k < 32; k++) s += av[k] * W[j * 32 + k];
            atomicAdd(orow + j, s);
        }
    }
}

// 6. tail: pad region [num_unique, E): r/c <- -1, attrs <- 0; write num_unique
__global__ void k_tail(float* __restrict__ out, int E) {
    int nu = g_nu;
    int stride = gridDim.x * blockDim.x;
    for (int i = nu + blockIdx.x * blockDim.x + threadIdx.x; i < E; i += stride) {
        out[i]     = -1.0f;
        out[E + i] = -1.0f;
    }
    float* out_attr = out + 2 * (size_t)E;
    size_t start = (size_t)nu * 64;
    size_t end   = (size_t)E * 64;
    for (size_t i = start + blockIdx.x * blockDim.x + threadIdx.x; i < end;
         i += (size_t)stride)
        out_attr[i] = 0.0f;
    if (blockIdx.x == 0 && threadIdx.x == 0)
        out[2 * (size_t)E + (size_t)E * 64] = (float)nu;
}

// ---------------------------------------------------------------------------
extern "C" void kernel_launch(void* const* d_in, const int* in_sizes, int n_in,
                              void* d_out, int out_size) {
    (void)n_in; (void)out_size;
    const int*   ei    = (const int*)d_in[0];
    const float* eattr = (const float*)d_in[1];
    const int*   ai    = (const int*)d_in[2];
    const float* aattr = (const float*)d_in[3];
    const float* W     = (const float*)d_in[4];
    const int Ee = in_sizes[0] / 2;
    const int Ea = in_sizes[2] / 2;
    const int E  = Ee + Ea;
    float* out = (float*)d_out;

    void *pka, *pkb, *ptmp;
    cudaGetSymbolAddress(&pka, g_k64_a);
    cudaGetSymbolAddress(&pkb, g_k64_b);
    cudaGetSymbolAddress(&ptmp, g_cub_temp);

    static bool attr_set = false;
    if (!attr_set) {
        cudaFuncSetAttribute(k_proj_arrwp,
                             cudaFuncAttributeMaxDynamicSharedMemorySize, SM_TOTAL);
        attr_set = true;
    }

    const int T = 256;
    const int nblk = (E + SCAN_TILE - 1) / SCAN_TILE;
    k_build_keys<<<(E + T - 1) / T, T>>>(ei, ai, Ee, Ea, nblk);

    // sort packed words by key bits only (payload rides along in low 21 bits)
    size_t tb = sizeof(g_cub_temp);
    cub::DeviceRadixSort::SortKeys(ptmp, tb,
                                   (const unsigned long long*)pka,
                                   (unsigned long long*)pkb,
                                   E, 21, 53);

    k_seg_scan<<<nblk, T>>>(E);
    k_copy_edges<<<(Ee * 16 + T - 1) / T, T>>>(ei, eattr, out, Ee, E);
    k_proj_arrwp<<<296, T, SM_TOTAL>>>(ai, aattr, W, out, Ee, Ea);
    k_scatter_dups<<<(E + T - 1) / T, T>>>(eattr, aattr, W, out, Ee, Ea);
    k_tail<<<256, T>>>(out, E);
}